// round 14
// baseline (speedup 1.0000x reference)
#include <cuda_runtime.h>
#include <cuda_bf16.h>
#include <cstdint>

#define BB 16
#define CC 256
#define TT 4096
#define KK 1024
#define BCT 16777216
#define NROWS 65536
#define WMARG 5.0e-4f
#define FINF 3.4e38f

// ---------------- device scratch ----------------
__device__ __align__(16) __nv_bfloat16 g_Ebf[KK * CC];  // bf16 codebook [k][d]
__device__ float g_cbnorm[KK];
__device__ float g_part[1024];
__device__ int   g_idx[NROWS];
__device__ int   g_cand[NROWS * 8];
__device__ unsigned char g_ccnt[NROWS];
__device__ int   g_flag[NROWS];
__device__ int   g_nflag;

// ---------------- helpers ----------------
__device__ __forceinline__ unsigned su32(const void* p) {
    unsigned a; asm("{ .reg .u64 t; cvta.to.shared.u64 t, %1; cvt.u32.u64 %0, t; }" : "=r"(a) : "l"(p)); return a;
}
__device__ __forceinline__ void ldm4(unsigned* r, unsigned addr) {
    asm volatile("ldmatrix.sync.aligned.m8n8.x4.shared.b16 {%0,%1,%2,%3}, [%4];"
        : "=r"(r[0]), "=r"(r[1]), "=r"(r[2]), "=r"(r[3]) : "r"(addr));
}
__device__ __forceinline__ void mma16816(float* c, const unsigned* a, const unsigned* b) {
    asm volatile("mma.sync.aligned.m16n8k16.row.col.f32.bf16.bf16.f32 "
        "{%0,%1,%2,%3}, {%4,%5,%6,%7}, {%8,%9}, {%0,%1,%2,%3};"
        : "+f"(c[0]), "+f"(c[1]), "+f"(c[2]), "+f"(c[3])
        : "r"(a[0]), "r"(a[1]), "r"(a[2]), "r"(a[3]), "r"(b[0]), "r"(b[1]));
}
__device__ __forceinline__ void cpasync16(unsigned dst, const void* src) {
    asm volatile("cp.async.cg.shared.global [%0], [%1], 16;" :: "r"(dst), "l"(src) : "memory");
}
#define CP_COMMIT() asm volatile("cp.async.commit_group;" ::: "memory")
#define CP_WAIT1()  asm volatile("cp.async.wait_group 1;" ::: "memory")
#define CP_WAIT0()  asm volatile("cp.async.wait_group 0;" ::: "memory")

__device__ __forceinline__ void top4_ins(float d, int k, float* td, int* tk) {
    if (d < td[3]) {
        td[3] = d; tk[3] = k;
        if (td[3] < td[2]) { float t = td[2]; td[2] = td[3]; td[3] = t; int u = tk[2]; tk[2] = tk[3]; tk[3] = u; }
        if (td[2] < td[1]) { float t = td[1]; td[1] = td[2]; td[2] = t; int u = tk[1]; tk[1] = tk[2]; tk[2] = u; }
        if (td[1] < td[0]) { float t = td[0]; td[0] = td[1]; td[1] = t; int u = tk[0]; tk[0] = tk[1]; tk[1] = u; }
    }
}

// smem layout (bytes) for vq_cand
#define PITCHB 528                 // 264 bf16 per row
#define SM_A    0                  // 128*528 = 67584
#define SM_B    67584              // 2 x 67584 = 135168
#define SM_NRM  202752             // 4096
#define SM_TOT  206848

// ---------------------------------------------------------------------------
// prep: bf16 codebook + norms (sequential fp32 FMA) + flag reset
// ---------------------------------------------------------------------------
__global__ void vq_prep(const float* __restrict__ cb) {
    int gid = blockIdx.x * 256 + threadIdx.x;
    #pragma unroll
    for (int r = 0; r < 4; r++) {
        int i = r * 65536 + gid;
        g_Ebf[i] = __float2bfloat16(cb[i]);
    }
    if (gid < KK) {
        const float* row = cb + gid * CC;
        float s = 0.f;
        #pragma unroll 8
        for (int d = 0; d < CC; d++) s = fmaf(row[d], row[d], s);
        g_cbnorm[gid] = s;
    }
    if (gid == 0) g_nflag = 0;
}

// ---------------------------------------------------------------------------
// candidate kernel v3: 256 threads (8 warps), CTA = 128 rows.
// Warp tile 32t x 64 codes (6 LDSM per 16 HMMA). B: 128-code chunks,
// cp.async double-buffered. Top-4 per (row, thread) lists + merge.
// ---------------------------------------------------------------------------
__global__ __launch_bounds__(256, 1)
void vq_cand(const float* __restrict__ x) {
    extern __shared__ char smem[];
    const unsigned smb = su32(smem);
    const int tid = threadIdx.x, wid = tid >> 5, l = tid & 31;
    const int wt = wid >> 1, wk = wid & 1;     // wt 0..3 (32 rows each), wk 0..1 (64 codes)
    const int b = blockIdx.x >> 5;
    const int t0 = (blockIdx.x & 31) * 128;
    const float* xb = x + (size_t)b * CC * TT + t0;

    // ---- norms to smem ----
    float* nrm_s = (float*)(smem + SM_NRM);
    #pragma unroll
    for (int r = 0; r < 4; r++) nrm_s[r * 256 + tid] = g_cbnorm[r * 256 + tid];

    // ---- build A tile (bf16, row-major [t][d], pitch 264 bf16) ----
    {
        float* scr = (float*)(smem + SM_B);           // B0 area as fp32 scratch [32][132]
        for (int pass = 0; pass < 8; pass++) {
            const int c0 = pass * 32;
            __syncthreads();
            #pragma unroll
            for (int it = 0; it < 4; it++) {
                int j = it * 256 + tid;               // 1024 float4 jobs
                int cl = j >> 5, t4 = (j & 31) << 2;
                *(float4*)(scr + cl * 132 + t4) =
                    *(const float4*)(xb + (size_t)(c0 + cl) * TT + t4);
            }
            __syncthreads();
            const int t = tid >> 1, half = tid & 1;   // t 0..127, 16 c's per thread
            unsigned hw[8];
            #pragma unroll
            for (int v = 0; v < 8; v++) {
                int c = half * 16 + 2 * v;
                float a0 = scr[c * 132 + t], a1 = scr[(c + 1) * 132 + t];
                __nv_bfloat16 h0 = __float2bfloat16(a0), h1 = __float2bfloat16(a1);
                hw[v] = ((unsigned)__bfloat16_as_ushort(h1) << 16) | __bfloat16_as_ushort(h0);
            }
            unsigned ah = smb + SM_A + (unsigned)(t * PITCHB + (c0 + half * 16) * 2);
            asm volatile("st.shared.v4.b32 [%0], {%1,%2,%3,%4};" :: "r"(ah), "r"(hw[0]), "r"(hw[1]), "r"(hw[2]), "r"(hw[3]) : "memory");
            asm volatile("st.shared.v4.b32 [%0], {%1,%2,%3,%4};" :: "r"(ah + 16), "r"(hw[4]), "r"(hw[5]), "r"(hw[6]), "r"(hw[7]) : "memory");
        }
        __syncthreads();
    }

    // ---- cp.async chunk 0 (128 codes x 256 d) into B0 ----
    {
        #pragma unroll
        for (int it = 0; it < 16; it++) {
            int j = it * 256 + tid;                    // 4096 x 16B jobs
            int code = j >> 5, g = j & 31;
            cpasync16(smb + SM_B + (unsigned)(code * PITCHB + g * 16),
                      g_Ebf + (size_t)code * CC + g * 8);
        }
        CP_COMMIT();
    }

    // ---- per-thread mma addresses ----
    const unsigned a_base = smb + SM_A +
        (unsigned)((wt * 32 + (l & 7) + ((l >> 3) & 1) * 8) * PITCHB + ((l >> 4) & 1) * 16);
    const unsigned nrow = (unsigned)((l >> 4) * 8 + (l & 7));
    const unsigned kcol = (unsigned)(((l >> 3) & 1) * 8);
    const unsigned b_thr = (unsigned)((wk * 64 + nrow) * PITCHB + kcol * 2);

    float c[2][8][4];
    #pragma unroll
    for (int i = 0; i < 2; i++)
        #pragma unroll
        for (int nt = 0; nt < 8; nt++)
            #pragma unroll
            for (int q = 0; q < 4; q++) c[i][nt][q] = 0.f;

    // 4 top4 lists: list = i*2 + qh  (row = wt*32 + i*16 + (l>>2) + 8*qh)
    float t4d[4][4]; int t4k[4][4];
    #pragma unroll
    for (int li = 0; li < 4; li++)
        #pragma unroll
        for (int j = 0; j < 4; j++) { t4d[li][j] = FINF; t4k[li][j] = 0; }

    for (int kc = 0; kc < 8; kc++) {
        if (kc < 7) {
            #pragma unroll
            for (int it = 0; it < 16; it++) {
                int j = it * 256 + tid;
                int code = j >> 5, g = j & 31;
                cpasync16(smb + SM_B + (unsigned)(((kc + 1) & 1) * 67584 + code * PITCHB + g * 16),
                          g_Ebf + (size_t)((kc + 1) * 128 + code) * CC + g * 8);
            }
            CP_COMMIT();
            CP_WAIT1();
        } else {
            CP_WAIT0();
        }
        __syncthreads();

        const unsigned bbase = smb + SM_B + (kc & 1) * 67584 + b_thr;
        #pragma unroll
        for (int s = 0; s < 16; s++) {
            unsigned a0[4], a1[4], b0[4], b1[4], b2[4], b3[4];
            ldm4(a0, a_base + s * 32);
            ldm4(a1, a_base + 16 * PITCHB + s * 32);
            ldm4(b0, bbase + s * 32);
            ldm4(b1, bbase + 16 * PITCHB + s * 32);
            ldm4(b2, bbase + 32 * PITCHB + s * 32);
            ldm4(b3, bbase + 48 * PITCHB + s * 32);
            mma16816(c[0][0], a0, b0); mma16816(c[0][1], a0, b0 + 2);
            mma16816(c[0][2], a0, b1); mma16816(c[0][3], a0, b1 + 2);
            mma16816(c[0][4], a0, b2); mma16816(c[0][5], a0, b2 + 2);
            mma16816(c[0][6], a0, b3); mma16816(c[0][7], a0, b3 + 2);
            mma16816(c[1][0], a1, b0); mma16816(c[1][1], a1, b0 + 2);
            mma16816(c[1][2], a1, b1); mma16816(c[1][3], a1, b1 + 2);
            mma16816(c[1][4], a1, b2); mma16816(c[1][5], a1, b2 + 2);
            mma16816(c[1][6], a1, b3); mma16816(c[1][7], a1, b3 + 2);
        }

        // epilogue: fine dist + top4 update; reset accums
        #pragma unroll
        for (int i = 0; i < 2; i++)
            #pragma unroll
            for (int nt = 0; nt < 8; nt++) {
                const int kbase = kc * 128 + wk * 64 + nt * 8 + (l & 3) * 2;
                #pragma unroll
                for (int q = 0; q < 4; q++) {
                    int k = kbase + (q & 1);
                    float dist = fmaf(-2.f, c[i][nt][q], nrm_s[k]);
                    top4_ins(dist, k, t4d[i * 2 + (q >> 1)], t4k[i * 2 + (q >> 1)]);
                    c[i][nt][q] = 0.f;
                }
            }
        __syncthreads();
    }

    // ---- dump per-thread top4 lists to smem (overlay on B buffer 0) ----
    float* cd = (float*)(smem + SM_B);          // [128][33]
    int*   ck = (int*)(smem + SM_B + 16896);    // [128][33]
    {
        const int slot = (wk * 4 + (l & 3)) * 4;
        #pragma unroll
        for (int li = 0; li < 4; li++) {
            const int r = wt * 32 + (li >> 1) * 16 + (l >> 2) + 8 * (li & 1);
            #pragma unroll
            for (int j = 0; j < 4; j++) {
                cd[r * 33 + slot + j] = t4d[li][j];
                ck[r * 33 + slot + j] = t4k[li][j];
            }
        }
    }
    __syncthreads();

    // ---- per-row merge (threads 0..127) ----
    if (tid < 128) {
        const int row = b * TT + t0 + tid;
        float bd = FINF; int bk = 0x7fffffff;
        #pragma unroll 8
        for (int e = 0; e < 32; e++) {
            float d = cd[tid * 33 + e]; int k = ck[tid * 33 + e];
            if (d < bd || (d == bd && k < bk)) { bd = d; bk = k; }
        }
        const float thr = bd + WMARG;
        int m = 0, ovf = 0;
        #pragma unroll 8
        for (int e = 0; e < 32; e++) {
            float d = cd[tid * 33 + e];
            if (d <= thr) {
                if (m < 8) g_cand[row * 8 + m] = ck[tid * 33 + e];
                m++;
                if ((e & 3) == 3) ovf = 1;   // a thread's 4th entry within margin
            }
        }
        if (m > 8) ovf = 1;
        g_idx[row] = bk;
        if (m > 1 || ovf) {
            g_ccnt[row] = ovf ? 255 : (unsigned char)m;
            int p = atomicAdd(&g_nflag, 1);
            g_flag[p] = row;
        }
    }
}

// ---------------------------------------------------------------------------
// exact rescore of flagged rows (bit-exact grid argmin; R2-validated recipe)
// ---------------------------------------------------------------------------
__global__ void vq_rescore(const float* __restrict__ x, const float* __restrict__ cb) {
    int gtid = blockIdx.x * 128 + threadIdx.x;
    int nf = g_nflag;
    for (int i = gtid; i < nf; i += 16384) {
        int row = g_flag[i];
        int bq = row >> 12, t = row & 4095;
        const float* xp = x + (size_t)bq * CC * TT + t;
        float a = 0.f;
        #pragma unroll 8
        for (int d = 0; d < CC; d++) {
            float v = xp[(size_t)d * TT];
            a = fmaf(v, v, a);
        }
        float bd = FINF; int bk = 0x7fffffff;
        int m = g_ccnt[row];
        if (m == 255) {
            for (int k = 0; k < KK; k++) {
                const float* e = cb + (size_t)k * CC;
                float s = 0.f;
                #pragma unroll 8
                for (int d = 0; d < CC; d++) s = fmaf(xp[(size_t)d * TT], e[d], s);
                float dist = (a + g_cbnorm[k]) - 2.0f * s;
                if (dist < bd || (dist == bd && k < bk)) { bd = dist; bk = k; }
            }
        } else {
            for (int ci = 0; ci < m; ci++) {
                int k = g_cand[row * 8 + ci];
                const float* e = cb + (size_t)k * CC;
                float s = 0.f;
                #pragma unroll 8
                for (int d = 0; d < CC; d++) s = fmaf(xp[(size_t)d * TT], e[d], s);
                float dist = (a + g_cbnorm[k]) - 2.0f * s;
                if (dist < bd || (dist == bd && k < bk)) { bd = dist; bk = k; }
            }
        }
        g_idx[row] = bk;
    }
}

// ---------------------------------------------------------------------------
// output kernel: straight-through quantized + loss partials + indices.
// qsT[c][t] pitch 65 (scalar access only); conflict-free main-loop reads.
// ---------------------------------------------------------------------------
#define QTP 65
__global__ __launch_bounds__(256, 1)
void vq_out(const float* __restrict__ x, const float* __restrict__ cb,
            float* __restrict__ out, int write_aux) {
    extern __shared__ float sm[];
    float* qsT = sm;                      // [256][65]
    float* red = sm + CC * QTP;           // [8]
    int* kidx  = (int*)(red + 8);         // [64]
    const int t0 = blockIdx.x * 64, b = blockIdx.y, tid = threadIdx.x;
    const float* xb = x + (size_t)b * CC * TT + t0;
    float* ob = out + (size_t)b * CC * TT + t0;

    if (tid < 64) kidx[tid] = g_idx[b * TT + t0 + tid];
    __syncthreads();
    #pragma unroll
    for (int it = 0; it < 16; it++) {
        int i = it * 256 + tid, t = i >> 6, f4 = (i & 63) << 2;
        float4 v = *(const float4*)(cb + (size_t)kidx[t] * CC + f4);
        qsT[(f4 + 0) * QTP + t] = v.x;
        qsT[(f4 + 1) * QTP + t] = v.y;
        qsT[(f4 + 2) * QTP + t] = v.z;
        qsT[(f4 + 3) * QTP + t] = v.w;
    }
    __syncthreads();

    float lsum = 0.f;
    #pragma unroll 4
    for (int it = 0; it < 16; it++) {
        int j = it * 256 + tid;
        int t = j & 63, cg = (j >> 6) << 2;
        #pragma unroll
        for (int u = 0; u < 4; u++) {
            int c = cg + u;
            float xv = xb[(size_t)c * TT + t];
            float q  = qsT[c * QTP + t];
            float d  = q - xv;
            lsum = fmaf(d, d, lsum);
            ob[(size_t)c * TT + t] = xv + d;
        }
    }
    #pragma unroll
    for (int off = 16; off > 0; off >>= 1)
        lsum += __shfl_xor_sync(0xffffffffu, lsum, off);
    if ((tid & 31) == 0) red[tid >> 5] = lsum;
    __syncthreads();
    if (tid == 0) {
        float s = 0.f;
        #pragma unroll
        for (int w = 0; w < 8; w++) s += red[w];
        g_part[blockIdx.y * gridDim.x + blockIdx.x] = s;
    }
    if (write_aux && tid < 64)
        out[(size_t)BCT + 1 + (size_t)b * TT + t0 + tid] = (float)kidx[tid];
}

__global__ void vq_finalize(float* __restrict__ out, int write_loss) {
    __shared__ float s[256];
    float v = 0.f;
    for (int i = threadIdx.x; i < 1024; i += 256) v += g_part[i];
    s[threadIdx.x] = v;
    __syncthreads();
    for (int off = 128; off > 0; off >>= 1) {
        if (threadIdx.x < off) s[threadIdx.x] += s[threadIdx.x + off];
        __syncthreads();
    }
    if (threadIdx.x == 0 && write_loss) out[BCT] = 1.25f * s[0] / 16777216.f;
}

// ---------------------------------------------------------------------------
extern "C" void kernel_launch(void* const* d_in, const int* in_sizes, int n_in,
                              void* d_out, int out_size) {
    const float* x  = (const float*)d_in[0];
    const float* cb = (const float*)d_in[1];
    float* out = (float*)d_out;
    const long long expected = (long long)BCT + 1 + NROWS;
    int write_aux = (out_size >= expected) ? 1 : 0;

    static int attr_set = 0;
    const int out_smem = (CC * QTP + 8 + 64) * 4;   // 67,168 B
    if (!attr_set) {
        cudaFuncSetAttribute(vq_cand, cudaFuncAttributeMaxDynamicSharedMemorySize, SM_TOT);
        cudaFuncSetAttribute(vq_out,  cudaFuncAttributeMaxDynamicSharedMemorySize, out_smem);
        attr_set = 1;
    }

    vq_prep<<<256, 256>>>(cb);
    vq_cand<<<512, 256, SM_TOT>>>(x);
    vq_rescore<<<128, 128>>>(x, cb);
    vq_out<<<dim3(64, 16), 256, out_smem>>>(x, cb, out, write_aux);
    vq_finalize<<<1, 256>>>(out, write_aux);
}

// round 15
// speedup vs baseline: 1.0424x; 1.0424x over previous
#include <cuda_runtime.h>
#include <cuda_bf16.h>
#include <cstdint>

#define BB 16
#define CC 256
#define TT 4096
#define KK 1024
#define BCT 16777216
#define NROWS 65536
#define WMARG 5.0e-4f
#define FINF 3.4e38f

// ---------------- device scratch ----------------
__device__ __align__(16) __nv_bfloat16 g_Ebf[KK * CC];  // bf16 codebook [k][d]
__device__ float g_cbnorm[KK];
__device__ float g_part[1024];
__device__ int   g_idx[NROWS];
__device__ int   g_cand[NROWS * 8];
__device__ unsigned char g_ccnt[NROWS];
__device__ int   g_flag[NROWS];
__device__ int   g_nflag;

// ---------------- helpers ----------------
__device__ __forceinline__ unsigned su32(const void* p) {
    unsigned a; asm("{ .reg .u64 t; cvta.to.shared.u64 t, %1; cvt.u32.u64 %0, t; }" : "=r"(a) : "l"(p)); return a;
}
__device__ __forceinline__ void ldm4(unsigned* r, unsigned addr) {
    asm volatile("ldmatrix.sync.aligned.m8n8.x4.shared.b16 {%0,%1,%2,%3}, [%4];"
        : "=r"(r[0]), "=r"(r[1]), "=r"(r[2]), "=r"(r[3]) : "r"(addr));
}
__device__ __forceinline__ void mma16816(float* c, const unsigned* a, const unsigned* b) {
    asm volatile("mma.sync.aligned.m16n8k16.row.col.f32.bf16.bf16.f32 "
        "{%0,%1,%2,%3}, {%4,%5,%6,%7}, {%8,%9}, {%0,%1,%2,%3};"
        : "+f"(c[0]), "+f"(c[1]), "+f"(c[2]), "+f"(c[3])
        : "r"(a[0]), "r"(a[1]), "r"(a[2]), "r"(a[3]), "r"(b[0]), "r"(b[1]));
}
__device__ __forceinline__ void cpasync16(unsigned dst, const void* src) {
    asm volatile("cp.async.cg.shared.global [%0], [%1], 16;" :: "r"(dst), "l"(src) : "memory");
}
#define CP_COMMIT() asm volatile("cp.async.commit_group;" ::: "memory")
#define CP_WAIT1()  asm volatile("cp.async.wait_group 1;" ::: "memory")
#define CP_WAIT0()  asm volatile("cp.async.wait_group 0;" ::: "memory")

__device__ __forceinline__ void top4_ins(float d, int k, float* td, int* tk) {
    if (d < td[3]) {
        td[3] = d; tk[3] = k;
        if (td[3] < td[2]) { float t = td[2]; td[2] = td[3]; td[3] = t; int u = tk[2]; tk[2] = tk[3]; tk[3] = u; }
        if (td[2] < td[1]) { float t = td[1]; td[1] = td[2]; td[2] = t; int u = tk[1]; tk[1] = tk[2]; tk[2] = u; }
        if (td[1] < td[0]) { float t = td[0]; td[0] = td[1]; td[1] = t; int u = tk[0]; tk[0] = tk[1]; tk[1] = u; }
    }
}

// smem layout (bytes) for vq_cand
#define PITCHB 528                 // 264 bf16 per row
#define SM_A    0                  // 128*528 = 67584
#define SM_B    67584              // 2 x 67584 = 135168
#define SM_NRM  202752             // 4096
#define SM_TOT  206848

// ---------------------------------------------------------------------------
// prep v2: vectorized bf16 convert + coalesced (smem-staged) norms.
// Norm arithmetic = sequential ascending-d fmaf chain, bit-identical to R2.
// grid 128 x 256.
// ---------------------------------------------------------------------------
__global__ void vq_prep(const float* __restrict__ cb) {
    const int tid = threadIdx.x, bid = blockIdx.x;
    const int gid = bid * 256 + tid;           // 0..32767
    // ---- convert: 8 floats -> 8 bf16 per thread (coalesced) ----
    {
        const float4* src = (const float4*)cb + (size_t)gid * 2;
        float4 v0 = src[0], v1 = src[1];
        unsigned u0 = ((unsigned)__bfloat16_as_ushort(__float2bfloat16(v0.y)) << 16) | __bfloat16_as_ushort(__float2bfloat16(v0.x));
        unsigned u1 = ((unsigned)__bfloat16_as_ushort(__float2bfloat16(v0.w)) << 16) | __bfloat16_as_ushort(__float2bfloat16(v0.z));
        unsigned u2 = ((unsigned)__bfloat16_as_ushort(__float2bfloat16(v1.y)) << 16) | __bfloat16_as_ushort(__float2bfloat16(v1.x));
        unsigned u3 = ((unsigned)__bfloat16_as_ushort(__float2bfloat16(v1.w)) << 16) | __bfloat16_as_ushort(__float2bfloat16(v1.z));
        uint4 o; o.x = u0; o.y = u1; o.z = u2; o.w = u3;
        ((uint4*)g_Ebf)[gid] = o;
    }
    // ---- norms: blocks 0..31 each handle 32 codebook rows ----
    if (bid < 32) {
        __shared__ float srow[8192];           // 32 rows x 256 floats = 32 KB
        const float4* base = (const float4*)(cb + (size_t)bid * 32 * CC);
        #pragma unroll
        for (int it = 0; it < 8; it++) {
            int j = it * 256 + tid;            // 2048 float4 jobs
            ((float4*)srow)[j] = base[j];
        }
        __syncthreads();
        if (tid < 32) {
            const float* r = srow + tid * CC;
            float s = 0.f;
            for (int d = 0; d < CC; d++) s = fmaf(r[d], r[d], s);   // sequential
            g_cbnorm[bid * 32 + tid] = s;
        }
    }
    if (gid == 0) g_nflag = 0;
}

// ---------------------------------------------------------------------------
// candidate kernel v4: 256 threads (8 warps), CTA = 128 rows.
// Warp tile 32t x 64 codes. B: 128-code chunks, cp.async double-buffered.
// Epilogue: branch-free 16-element FMNMX min-tree gate; only groups that can
// change the top-4 run the sorted insert -> identical top-4 lists, far fewer
// issued instructions.
// ---------------------------------------------------------------------------
__global__ __launch_bounds__(256, 1)
void vq_cand(const float* __restrict__ x) {
    extern __shared__ char smem[];
    const unsigned smb = su32(smem);
    const int tid = threadIdx.x, wid = tid >> 5, l = tid & 31;
    const int wt = wid >> 1, wk = wid & 1;     // wt 0..3 (32 rows each), wk 0..1 (64 codes)
    const int b = blockIdx.x >> 5;
    const int t0 = (blockIdx.x & 31) * 128;
    const float* xb = x + (size_t)b * CC * TT + t0;

    // ---- norms to smem ----
    float* nrm_s = (float*)(smem + SM_NRM);
    #pragma unroll
    for (int r = 0; r < 4; r++) nrm_s[r * 256 + tid] = g_cbnorm[r * 256 + tid];

    // ---- build A tile (bf16, row-major [t][d], pitch 264 bf16) ----
    {
        float* scr = (float*)(smem + SM_B);           // B0 area as fp32 scratch [32][132]
        for (int pass = 0; pass < 8; pass++) {
            const int c0 = pass * 32;
            __syncthreads();
            #pragma unroll
            for (int it = 0; it < 4; it++) {
                int j = it * 256 + tid;               // 1024 float4 jobs
                int cl = j >> 5, t4 = (j & 31) << 2;
                *(float4*)(scr + cl * 132 + t4) =
                    *(const float4*)(xb + (size_t)(c0 + cl) * TT + t4);
            }
            __syncthreads();
            const int t = tid >> 1, half = tid & 1;   // t 0..127, 16 c's per thread
            unsigned hw[8];
            #pragma unroll
            for (int v = 0; v < 8; v++) {
                int c = half * 16 + 2 * v;
                float a0 = scr[c * 132 + t], a1 = scr[(c + 1) * 132 + t];
                __nv_bfloat16 h0 = __float2bfloat16(a0), h1 = __float2bfloat16(a1);
                hw[v] = ((unsigned)__bfloat16_as_ushort(h1) << 16) | __bfloat16_as_ushort(h0);
            }
            unsigned ah = smb + SM_A + (unsigned)(t * PITCHB + (c0 + half * 16) * 2);
            asm volatile("st.shared.v4.b32 [%0], {%1,%2,%3,%4};" :: "r"(ah), "r"(hw[0]), "r"(hw[1]), "r"(hw[2]), "r"(hw[3]) : "memory");
            asm volatile("st.shared.v4.b32 [%0], {%1,%2,%3,%4};" :: "r"(ah + 16), "r"(hw[4]), "r"(hw[5]), "r"(hw[6]), "r"(hw[7]) : "memory");
        }
        __syncthreads();
    }

    // ---- cp.async chunk 0 (128 codes x 256 d) into B0 ----
    {
        #pragma unroll
        for (int it = 0; it < 16; it++) {
            int j = it * 256 + tid;                    // 4096 x 16B jobs
            int code = j >> 5, g = j & 31;
            cpasync16(smb + SM_B + (unsigned)(code * PITCHB + g * 16),
                      g_Ebf + (size_t)code * CC + g * 8);
        }
        CP_COMMIT();
    }

    // ---- per-thread mma addresses ----
    const unsigned a_base = smb + SM_A +
        (unsigned)((wt * 32 + (l & 7) + ((l >> 3) & 1) * 8) * PITCHB + ((l >> 4) & 1) * 16);
    const unsigned nrow = (unsigned)((l >> 4) * 8 + (l & 7));
    const unsigned kcol = (unsigned)(((l >> 3) & 1) * 8);
    const unsigned b_thr = (unsigned)((wk * 64 + nrow) * PITCHB + kcol * 2);

    float c[2][8][4];
    #pragma unroll
    for (int i = 0; i < 2; i++)
        #pragma unroll
        for (int nt = 0; nt < 8; nt++)
            #pragma unroll
            for (int q = 0; q < 4; q++) c[i][nt][q] = 0.f;

    // 4 top4 lists: list li = i*2 + qh  (row = wt*32 + i*16 + (l>>2) + 8*qh)
    float t4d[4][4]; int t4k[4][4];
    #pragma unroll
    for (int li = 0; li < 4; li++)
        #pragma unroll
        for (int j = 0; j < 4; j++) { t4d[li][j] = FINF; t4k[li][j] = 0; }

    for (int kc = 0; kc < 8; kc++) {
        if (kc < 7) {
            #pragma unroll
            for (int it = 0; it < 16; it++) {
                int j = it * 256 + tid;
                int code = j >> 5, g = j & 31;
                cpasync16(smb + SM_B + (unsigned)(((kc + 1) & 1) * 67584 + code * PITCHB + g * 16),
                          g_Ebf + (size_t)((kc + 1) * 128 + code) * CC + g * 8);
            }
            CP_COMMIT();
            CP_WAIT1();
        } else {
            CP_WAIT0();
        }
        __syncthreads();

        const unsigned bbase = smb + SM_B + (kc & 1) * 67584 + b_thr;
        #pragma unroll
        for (int s = 0; s < 16; s++) {
            unsigned a0[4], a1[4], b0[4], b1[4], b2[4], b3[4];
            ldm4(a0, a_base + s * 32);
            ldm4(a1, a_base + 16 * PITCHB + s * 32);
            ldm4(b0, bbase + s * 32);
            ldm4(b1, bbase + 16 * PITCHB + s * 32);
            ldm4(b2, bbase + 32 * PITCHB + s * 32);
            ldm4(b3, bbase + 48 * PITCHB + s * 32);
            mma16816(c[0][0], a0, b0); mma16816(c[0][1], a0, b0 + 2);
            mma16816(c[0][2], a0, b1); mma16816(c[0][3], a0, b1 + 2);
            mma16816(c[0][4], a0, b2); mma16816(c[0][5], a0, b2 + 2);
            mma16816(c[0][6], a0, b3); mma16816(c[0][7], a0, b3 + 2);
            mma16816(c[1][0], a1, b0); mma16816(c[1][1], a1, b0 + 2);
            mma16816(c[1][2], a1, b1); mma16816(c[1][3], a1, b1 + 2);
            mma16816(c[1][4], a1, b2); mma16816(c[1][5], a1, b2 + 2);
            mma16816(c[1][6], a1, b3); mma16816(c[1][7], a1, b3 + 2);
        }

        // ---- epilogue: group min-tree gate + (rare) exact top4 insert ----
        #pragma unroll
        for (int i = 0; i < 2; i++) {
            #pragma unroll
            for (int qh = 0; qh < 2; qh++) {
                const int li = i * 2 + qh;
                float d[16];
                #pragma unroll
                for (int nt = 0; nt < 8; nt++) {
                    #pragma unroll
                    for (int qb = 0; qb < 2; qb++) {
                        const int q = qh * 2 + qb;
                        const int k = kc * 128 + wk * 64 + nt * 8 + (l & 3) * 2 + qb;
                        d[nt * 2 + qb] = fmaf(-2.f, c[i][nt][q], nrm_s[k]);
                        c[i][nt][q] = 0.f;
                    }
                }
                float m = fminf(
                    fminf(fminf(fminf(d[0], d[1]), fminf(d[2], d[3])),
                          fminf(fminf(d[4], d[5]), fminf(d[6], d[7]))),
                    fminf(fminf(fminf(d[8], d[9]), fminf(d[10], d[11])),
                          fminf(fminf(d[12], d[13]), fminf(d[14], d[15]))));
                if (m < t4d[li][3]) {
                    #pragma unroll
                    for (int j = 0; j < 16; j++) {
                        const int k = kc * 128 + wk * 64 + (j >> 1) * 8 + (l & 3) * 2 + (j & 1);
                        top4_ins(d[j], k, t4d[li], t4k[li]);
                    }
                }
            }
        }
        __syncthreads();
    }

    // ---- dump per-thread top4 lists to smem (overlay on B buffer 0) ----
    float* cd = (float*)(smem + SM_B);          // [128][33]
    int*   ck = (int*)(smem + SM_B + 16896);    // [128][33]
    {
        const int slot = (wk * 4 + (l & 3)) * 4;
        #pragma unroll
        for (int li = 0; li < 4; li++) {
            const int r = wt * 32 + (li >> 1) * 16 + (l >> 2) + 8 * (li & 1);
            #pragma unroll
            for (int j = 0; j < 4; j++) {
                cd[r * 33 + slot + j] = t4d[li][j];
                ck[r * 33 + slot + j] = t4k[li][j];
            }
        }
    }
    __syncthreads();

    // ---- per-row merge (threads 0..127) ----
    if (tid < 128) {
        const int row = b * TT + t0 + tid;
        float bd = FINF; int bk = 0x7fffffff;
        #pragma unroll 8
        for (int e = 0; e < 32; e++) {
            float d = cd[tid * 33 + e]; int k = ck[tid * 33 + e];
            if (d < bd || (d == bd && k < bk)) { bd = d; bk = k; }
        }
        const float thr = bd + WMARG;
        int m = 0, ovf = 0;
        #pragma unroll 8
        for (int e = 0; e < 32; e++) {
            float d = cd[tid * 33 + e];
            if (d <= thr) {
                if (m < 8) g_cand[row * 8 + m] = ck[tid * 33 + e];
                m++;
                if ((e & 3) == 3) ovf = 1;   // a thread's 4th entry within margin
            }
        }
        if (m > 8) ovf = 1;
        g_idx[row] = bk;
        if (m > 1 || ovf) {
            g_ccnt[row] = ovf ? 255 : (unsigned char)m;
            int p = atomicAdd(&g_nflag, 1);
            g_flag[p] = row;
        }
    }
}

// ---------------------------------------------------------------------------
// exact rescore of flagged rows (bit-exact grid argmin; R2-validated recipe)
// ---------------------------------------------------------------------------
__global__ void vq_rescore(const float* __restrict__ x, const float* __restrict__ cb) {
    int gtid = blockIdx.x * 128 + threadIdx.x;
    int nf = g_nflag;
    for (int i = gtid; i < nf; i += 16384) {
        int row = g_flag[i];
        int bq = row >> 12, t = row & 4095;
        const float* xp = x + (size_t)bq * CC * TT + t;
        float a = 0.f;
        #pragma unroll 8
        for (int d = 0; d < CC; d++) {
            float v = xp[(size_t)d * TT];
            a = fmaf(v, v, a);
        }
        float bd = FINF; int bk = 0x7fffffff;
        int m = g_ccnt[row];
        if (m == 255) {
            for (int k = 0; k < KK; k++) {
                const float* e = cb + (size_t)k * CC;
                float s = 0.f;
                #pragma unroll 8
                for (int d = 0; d < CC; d++) s = fmaf(xp[(size_t)d * TT], e[d], s);
                float dist = (a + g_cbnorm[k]) - 2.0f * s;
                if (dist < bd || (dist == bd && k < bk)) { bd = dist; bk = k; }
            }
        } else {
            for (int ci = 0; ci < m; ci++) {
                int k = g_cand[row * 8 + ci];
                const float* e = cb + (size_t)k * CC;
                float s = 0.f;
                #pragma unroll 8
                for (int d = 0; d < CC; d++) s = fmaf(xp[(size_t)d * TT], e[d], s);
                float dist = (a + g_cbnorm[k]) - 2.0f * s;
                if (dist < bd || (dist == bd && k < bk)) { bd = dist; bk = k; }
            }
        }
        g_idx[row] = bk;
    }
}

// ---------------------------------------------------------------------------
// output kernel: straight-through quantized + loss partials + indices.
// qsT[c][t] pitch 65 (scalar access only); conflict-free main-loop reads.
// ---------------------------------------------------------------------------
#define QTP 65
__global__ __launch_bounds__(256, 1)
void vq_out(const float* __restrict__ x, const float* __restrict__ cb,
            float* __restrict__ out, int write_aux) {
    extern __shared__ float sm[];
    float* qsT = sm;                      // [256][65]
    float* red = sm + CC * QTP;           // [8]
    int* kidx  = (int*)(red + 8);         // [64]
    const int t0 = blockIdx.x * 64, b = blockIdx.y, tid = threadIdx.x;
    const float* xb = x + (size_t)b * CC * TT + t0;
    float* ob = out + (size_t)b * CC * TT + t0;

    if (tid < 64) kidx[tid] = g_idx[b * TT + t0 + tid];
    __syncthreads();
    #pragma unroll
    for (int it = 0; it < 16; it++) {
        int i = it * 256 + tid, t = i >> 6, f4 = (i & 63) << 2;
        float4 v = *(const float4*)(cb + (size_t)kidx[t] * CC + f4);
        qsT[(f4 + 0) * QTP + t] = v.x;
        qsT[(f4 + 1) * QTP + t] = v.y;
        qsT[(f4 + 2) * QTP + t] = v.z;
        qsT[(f4 + 3) * QTP + t] = v.w;
    }
    __syncthreads();

    float lsum = 0.f;
    #pragma unroll 4
    for (int it = 0; it < 16; it++) {
        int j = it * 256 + tid;
        int t = j & 63, cg = (j >> 6) << 2;
        #pragma unroll
        for (int u = 0; u < 4; u++) {
            int c = cg + u;
            float xv = xb[(size_t)c * TT + t];
            float q  = qsT[c * QTP + t];
            float d  = q - xv;
            lsum = fmaf(d, d, lsum);
            ob[(size_t)c * TT + t] = xv + d;
        }
    }
    #pragma unroll
    for (int off = 16; off > 0; off >>= 1)
        lsum += __shfl_xor_sync(0xffffffffu, lsum, off);
    if ((tid & 31) == 0) red[tid >> 5] = lsum;
    __syncthreads();
    if (tid == 0) {
        float s = 0.f;
        #pragma unroll
        for (int w = 0; w < 8; w++) s += red[w];
        g_part[blockIdx.y * gridDim.x + blockIdx.x] = s;
    }
    if (write_aux && tid < 64)
        out[(size_t)BCT + 1 + (size_t)b * TT + t0 + tid] = (float)kidx[tid];
}

__global__ void vq_finalize(float* __restrict__ out, int write_loss) {
    __shared__ float s[256];
    float v = 0.f;
    for (int i = threadIdx.x; i < 1024; i += 256) v += g_part[i];
    s[threadIdx.x] = v;
    __syncthreads();
    for (int off = 128; off > 0; off >>= 1) {
        if (threadIdx.x < off) s[threadIdx.x] += s[threadIdx.x + off];
        __syncthreads();
    }
    if (threadIdx.x == 0 && write_loss) out[BCT] = 1.25f * s[0] / 16777216.f;
}

// ---------------------------------------------------------------------------
extern "C" void kernel_launch(void* const* d_in, const int* in_sizes, int n_in,
                              void* d_out, int out_size) {
    const float* x  = (const float*)d_in[0];
    const float* cb = (const float*)d_in[1];
    float* out = (float*)d_out;
    const long long expected = (long long)BCT + 1 + NROWS;
    int write_aux = (out_size >= expected) ? 1 : 0;

    static int attr_set = 0;
    const int out_smem = (CC * QTP + 8 + 64) * 4;   // 67,168 B
    if (!attr_set) {
        cudaFuncSetAttribute(vq_cand, cudaFuncAttributeMaxDynamicSharedMemorySize, SM_TOT);
        cudaFuncSetAttribute(vq_out,  cudaFuncAttributeMaxDynamicSharedMemorySize, out_smem);
        attr_set = 1;
    }

    vq_prep<<<128, 256>>>(cb);
    vq_cand<<<512, 256, SM_TOT>>>(x);
    vq_rescore<<<128, 128>>>(x, cb);
    vq_out<<<dim3(64, 16), 256, out_smem>>>(x, cb, out, write_aux);
    vq_finalize<<<1, 256>>>(out, write_aux);
}